// round 12
// baseline (speedup 1.0000x reference)
#include <cuda_runtime.h>

#define T 256
#define B 128
#define D 1024
#define K 21
#define TB (T * B)
#define TBK (TB * K)

#define DSPLIT 4
#define DCHUNK (D / DSPLIT)      // 256
#define DC 32
#define NSTAGE (DCHUNK / DC)     // 8
#define GROWS 128
#define GT 96

#define TCH 32                   // scan chunk (t's)
#define NCH (T / TCH)            // 8
#define CHUNK_TARGET 128u        // 32 rowblocks x 4 splits

typedef unsigned long long ull;

// g_part layout: [split][b][t][k]
__device__ float g_part[DSPLIT * TBK];
__device__ float g_loss_partial[B];
__device__ unsigned g_ticket = 0;
__device__ unsigned g_chunk_done[NCH];

__device__ __forceinline__ ull ffma2(ull a, ull b, ull c) {
    ull d;
    asm("fma.rn.f32x2 %0, %1, %2, %3;" : "=l"(d) : "l"(a), "l"(b), "l"(c));
    return d;
}
__device__ __forceinline__ ull pack2(float x, float y) {
    ull r;
    asm("mov.b64 %0, {%1, %2};" : "=l"(r) : "f"(x), "f"(y));
    return r;
}
__device__ __forceinline__ float2 unpack2(ull v) {
    float2 f;
    asm("mov.b64 {%0, %1}, %2;" : "=f"(f.x), "=f"(f.y) : "l"(v));
    return f;
}
__device__ __forceinline__ float max21(const float* v) {
    float a[11];
#pragma unroll
    for (int i = 0; i < 10; i++) a[i] = fmaxf(v[2 * i], v[2 * i + 1]);
    a[10] = v[20];
    float bb[6];
#pragma unroll
    for (int i = 0; i < 5; i++) bb[i] = fmaxf(a[2 * i], a[2 * i + 1]);
    bb[5] = a[10];
    float c0 = fmaxf(bb[0], bb[1]);
    float c1 = fmaxf(bb[2], bb[3]);
    float c2 = fmaxf(bb[4], bb[5]);
    return fmaxf(fmaxf(c0, c1), c2);
}

// Scan smem layout (floats unless noted)
#define SC_STRIDE 24
#define SMEM_EM     0
#define SMEM_SC     (T * K)
#define SMEM_TRANS  (SMEM_SC + T * SC_STRIDE)
#define SMEM_RMAX   (SMEM_TRANS + 444)
#define SMEM_SVF    (SMEM_RMAX + T)
#define SMEM_WB     (SMEM_SVF + 32)
#define SMEM_FLOATS (SMEM_WB + 64)
#define SMEM_HIST_B (SMEM_FLOATS * 4)
#define SMEM_PATH_B (SMEM_HIST_B + (T - 1) * K)
#define SMEM_TOTAL_B (SMEM_PATH_B + T + 16)

__global__ __launch_bounds__(GT, 4) void fused_kernel(
    const float* __restrict__ A,      // [TB, D], row = t*B + b
    const float* __restrict__ Wg,     // [D, K]
    const int*   __restrict__ tags,   // [T, B]
    const float* __restrict__ start,
    const float* __restrict__ endv,
    const float* __restrict__ trans,
    const float* __restrict__ bias,
    float* __restrict__ out)
{
    extern __shared__ __align__(16) char smraw[];
    const int tid  = threadIdx.x;
    const int warp = tid >> 5;
    const int lane = tid & 31;

    if (blockIdx.x >= B) {
        // ================= GEMM role (frozen R7 core) =================
        ull*        a_sh = (ull*)smraw;                       // DC*65
        ulonglong2* w_sh = (ulonglong2*)(smraw + DC * 65 * 8);// K*16

        const int gid    = blockIdx.x - B;
        const int kg     = warp;
        const int rg     = lane;
        const int rowblk = gid >> 2;        // == t
        const int split  = gid & 3;
        const int row0   = rowblk * GROWS;
        const int dbase  = split * DCHUNK;

        float4 apf[11];
        float2 wpf[4];

#pragma unroll
        for (int j = 0; j < 11; j++) {
            int i = tid + j * GT;
            if (i < 1024) {
                int r = i >> 3, dq = i & 7;
                apf[j] = *(const float4*)(A + (size_t)(row0 + r) * D + dbase + dq * 4);
            }
        }
#pragma unroll
        for (int j = 0; j < 4; j++) {
            int i = tid + j * GT;
            if (i < K * 16) {
                int k = i >> 4, dd2 = i & 15;
                int d0 = dbase + dd2 * 2;
                wpf[j].x = Wg[(size_t)d0 * K + k];
                wpf[j].y = Wg[(size_t)(d0 + 1) * K + k];
            }
        }

        ull acc0[7], acc1[7];
#pragma unroll
        for (int k = 0; k < 7; k++) { acc0[k] = 0ull; acc1[k] = 0ull; }

        for (int s = 0; s < NSTAGE; s++) {
            __syncthreads();
#pragma unroll
            for (int j = 0; j < 11; j++) {
                int i = tid + j * GT;
                if (i < 1024) {
                    int r = i >> 3, dq = i & 7;
                    int half = r >> 6, rl = r & 63;
                    ((float*)&a_sh[(dq * 4 + 0) * 65 + rl])[half] = apf[j].x;
                    ((float*)&a_sh[(dq * 4 + 1) * 65 + rl])[half] = apf[j].y;
                    ((float*)&a_sh[(dq * 4 + 2) * 65 + rl])[half] = apf[j].z;
                    ((float*)&a_sh[(dq * 4 + 3) * 65 + rl])[half] = apf[j].w;
                }
            }
#pragma unroll
            for (int j = 0; j < 4; j++) {
                int i = tid + j * GT;
                if (i < K * 16) {
                    int k = i >> 4, dd2 = i & 15;
                    w_sh[k * 16 + dd2] =
                        make_ulonglong2(pack2(wpf[j].x, wpf[j].x), pack2(wpf[j].y, wpf[j].y));
                }
            }
            if (s + 1 < NSTAGE) {
                int dcn = dbase + (s + 1) * DC;
#pragma unroll
                for (int j = 0; j < 11; j++) {
                    int i = tid + j * GT;
                    if (i < 1024) {
                        int r = i >> 3, dq = i & 7;
                        apf[j] = *(const float4*)(A + (size_t)(row0 + r) * D + dcn + dq * 4);
                    }
                }
#pragma unroll
                for (int j = 0; j < 4; j++) {
                    int i = tid + j * GT;
                    if (i < K * 16) {
                        int k = i >> 4, dd2 = i & 15;
                        int d0 = dcn + dd2 * 2;
                        wpf[j].x = Wg[(size_t)d0 * K + k];
                        wpf[j].y = Wg[(size_t)(d0 + 1) * K + k];
                    }
                }
            }
            __syncthreads();
            const ulonglong2* wk = w_sh + kg * 7 * 16;
#pragma unroll
            for (int dd2 = 0; dd2 < 16; dd2++) {
                ull a00 = a_sh[(2 * dd2) * 65 + rg];
                ull a01 = a_sh[(2 * dd2) * 65 + rg + 32];
                ull a10 = a_sh[(2 * dd2 + 1) * 65 + rg];
                ull a11 = a_sh[(2 * dd2 + 1) * 65 + rg + 32];
#pragma unroll
                for (int kk = 0; kk < 7; kk++) {
                    ulonglong2 wv = wk[kk * 16 + dd2];
                    acc0[kk] = ffma2(a00, wv.x, acc0[kk]);
                    acc0[kk] = ffma2(a10, wv.y, acc0[kk]);
                    acc1[kk] = ffma2(a01, wv.x, acc1[kk]);
                    acc1[kk] = ffma2(a11, wv.y, acc1[kk]);
                }
            }
        }

        __syncthreads();
        float* e_sh = (float*)a_sh;
#pragma unroll
        for (int kk = 0; kk < 7; kk++) {
            int k = kg * 7 + kk;
            float2 v0 = unpack2(acc0[kk]);
            float2 v1 = unpack2(acc1[kk]);
            e_sh[(rg)      * K + k] = v0.x;
            e_sh[(rg + 64) * K + k] = v0.y;
            e_sh[(rg + 32) * K + k] = v1.x;
            e_sh[(rg + 96) * K + k] = v1.y;
        }
        __syncthreads();
        float* gp = g_part + (size_t)split * TBK;
#pragma unroll
        for (int j = 0; j < (GROWS * K) / GT; j++) {
            int e = tid + j * GT;
            int bb = e / K;
            int k  = e - bb * K;
            gp[((size_t)bb * T + rowblk) * K + k] = e_sh[e];
        }
        __syncthreads();
        if (tid == 0) {
            __threadfence();
            atomicAdd(&g_chunk_done[rowblk >> 5], 1u);
        }
        return;
    }

    // ====================== SCAN role (bid < B) ======================
    float* em_s    = (float*)smraw + SMEM_EM;
    float* sc_s    = (float*)smraw + SMEM_SC;
    float* trans_s = (float*)smraw + SMEM_TRANS;
    float* rmax_s  = (float*)smraw + SMEM_RMAX;
    float* svf     = (float*)smraw + SMEM_SVF;
    float* wb0     = (float*)smraw + SMEM_WB;
    float* wb1     = (float*)smraw + SMEM_WB + 32;
    unsigned char* hist = (unsigned char*)smraw + SMEM_HIST_B;
    unsigned char* path = (unsigned char*)smraw + SMEM_PATH_B;

    const int b    = blockIdx.x;
    const bool act = (lane < K);
    const float NEG = -1e30f;
    const unsigned FULL = 0xffffffffu;

    __shared__ float bias_s[K];
    if (tid < K) bias_s[tid] = bias[tid];
    for (int i = tid; i < K * K; i += GT) trans_s[i] = trans[i];

    // tags + prefix masks (each of the 3 warps computes its own copy)
    int myt[8];
    unsigned mw[8];
#pragma unroll
    for (int j = 0; j < 8; j++) {
        myt[j] = tags[(j * 32 + lane) * B + b];
        mw[j]  = __ballot_sync(FULL, myt[j] != 0);
    }
    int len = 0;
#pragma unroll
    for (int j = 0; j < 8; j++) len += __popc(mw[j]);
    const int nch = (len + TCH - 1) / TCH;
    __syncthreads();

    // per-warp constant tables
    float tc[K], et[K];
    if (warp != 1) {
#pragma unroll
        for (int i = 0; i < K; i++) tc[i] = act ? trans_s[i * K + lane] : 0.0f;
    } else {
#pragma unroll
        for (int i = 0; i < K; i++) et[i] = act ? __expf(trans_s[i * K + lane]) : 0.0f;
    }

    float w = 0.0f, C = 0.0f;    // forward state (warp 1)

    for (int c = 0; c < nch; c++) {
        // ---- wait for gemm chunk c, then stage it ----
        if (tid == 0) {
            unsigned ns = 32;
            while (*(volatile unsigned*)&g_chunk_done[c] < CHUNK_TARGET) {
                __nanosleep(ns);
                if (ns < 256) ns += 32;
            }
            __threadfence();
        }
        __syncthreads();
        {
            const int base_f = c * TCH * K;           // multiple of 672 (==0 mod 21)
            const size_t gbase = (size_t)b * T * K + base_f;
            const float4* p0 = (const float4*)(g_part + gbase);
            const float4* p1 = (const float4*)(g_part + gbase + TBK);
            const float4* p2 = (const float4*)(g_part + gbase + 2 * (size_t)TBK);
            const float4* p3 = (const float4*)(g_part + gbase + 3 * (size_t)TBK);
            float4* dst = (float4*)(em_s + base_f);
            for (int i = tid; i < (TCH * K) / 4; i += GT) {
                float4 a = p0[i], cc = p1[i], d = p2[i], e = p3[i];
                int k0 = (4 * i) % K;
                int k1 = k0 + 1; if (k1 >= K) k1 -= K;
                int k2 = k1 + 1; if (k2 >= K) k2 -= K;
                int k3 = k2 + 1; if (k3 >= K) k3 -= K;
                float4 r;
                r.x = ((a.x + cc.x) + (d.x + e.x)) + bias_s[k0];
                r.y = ((a.y + cc.y) + (d.y + e.y)) + bias_s[k1];
                r.z = ((a.z + cc.z) + (d.z + e.z)) + bias_s[k2];
                r.w = ((a.w + cc.w) + (d.w + e.w)) + bias_s[k3];
                dst[i] = r;
            }
            if (tid < TCH) {
                int t = c * TCH + tid;
                const float* p = em_s + t * K;
                float m = p[0];
#pragma unroll
                for (int i = 1; i < K; i++) m = fmaxf(m, p[i]);
                rmax_s[t] = m;
            }
        }
        __syncthreads();

        const int t0 = (c == 0) ? 1 : c * TCH;
        const int t1 = min(len, (c + 1) * TCH);

        if (warp == 0) {
            // ---------- Viterbi chain (state in sc_s) ----------
            if (c == 0) {
                if (act) sc_s[lane] = start[lane] + em_s[lane];
                __syncwarp();
            }
            if (t0 < t1) {
                float emN = act ? em_s[t0 * K + lane] : 0.0f;
                for (int t = t0; t < t1; t++) {
                    const float em_t = emN;
                    if (t + 1 < t1) emN = act ? em_s[(t + 1) * K + lane] : 0.0f;
                    const float4* sp = (const float4*)(sc_s + (t - 1) * SC_STRIDE);
                    float4 q0 = sp[0], q1 = sp[1], q2 = sp[2], q3 = sp[3], q4 = sp[4], q5 = sp[5];
                    float s[24] = { q0.x,q0.y,q0.z,q0.w, q1.x,q1.y,q1.z,q1.w,
                                    q2.x,q2.y,q2.z,q2.w, q3.x,q3.y,q3.z,q3.w,
                                    q4.x,q4.y,q4.z,q4.w, q5.x,q5.y,q5.z,q5.w };
                    float v[21];
#pragma unroll
                    for (int i = 0; i < K; i++) v[i] = s[i] + tc[i];
                    const float m = max21(v);
                    if (act) sc_s[t * SC_STRIDE + lane] = m + em_t;
                    __syncwarp();
                }
            }
        } else if (warp == 1) {
            // ---------- Forward chain (renorm every 8) ----------
            if (c == 0) {
                float sc0 = act ? (start[lane] + em_s[lane]) : NEG;
                float r0 = sc0;
#pragma unroll
                for (int o = 16; o > 0; o >>= 1) r0 = fmaxf(r0, __shfl_xor_sync(FULL, r0, o));
                w = act ? __expf(sc0 - r0) : 0.0f;
                C = r0;
            }
            if (t0 < t1) {
                float rN   = rmax_s[t0];
                float eemN = act ? __expf(em_s[t0 * K + lane] - rN) : 0.0f;
                for (int t = t0; t < t1; t++) {
                    const float eem = eemN;
                    const float r   = rN;
                    float* buf = (t & 1) ? wb1 : wb0;
                    if (act) buf[lane] = w;
                    __syncwarp();
                    if (t + 1 < t1) {
                        rN   = rmax_s[t + 1];
                        eemN = act ? __expf(em_s[(t + 1) * K + lane] - rN) : 0.0f;
                    }
                    const float4* bp = (const float4*)buf;
                    float4 q0 = bp[0], q1 = bp[1], q2 = bp[2], q3 = bp[3], q4 = bp[4], q5 = bp[5];
                    float wv[24] = { q0.x,q0.y,q0.z,q0.w, q1.x,q1.y,q1.z,q1.w,
                                     q2.x,q2.y,q2.z,q2.w, q3.x,q3.y,q3.z,q3.w,
                                     q4.x,q4.y,q4.z,q4.w, q5.x,q5.y,q5.z,q5.w };
                    float d0 = 0.f, d1 = 0.f, d2 = 0.f;
#pragma unroll
                    for (int i = 0; i < 7; i++)   d0 = fmaf(wv[i], et[i], d0);
#pragma unroll
                    for (int i = 7; i < 14; i++)  d1 = fmaf(wv[i], et[i], d1);
#pragma unroll
                    for (int i = 14; i < 21; i++) d2 = fmaf(wv[i], et[i], d2);
                    w = ((d0 + d1) + d2) * eem;
                    C += r;
                    if ((t & 7) == 7) {
                        float S = w;
#pragma unroll
                        for (int o = 16; o > 0; o >>= 1) S += __shfl_xor_sync(FULL, S, o);
                        float rs;
                        asm("rcp.approx.f32 %0, %1;" : "=f"(rs) : "f"(S));
                        w *= rs;
                        C += __logf(S);
                    }
                }
            }
        } else {
            // ---------- Hist recompute for PREVIOUS chunk ----------
            if (c > 0) {
                int h0 = max(1, (c - 1) * TCH);
                int h1 = min(len, c * TCH);
                for (int t = h0; t < h1; t++) {
                    const float4* sp = (const float4*)(sc_s + (t - 1) * SC_STRIDE);
                    float4 q0 = sp[0], q1 = sp[1], q2 = sp[2], q3 = sp[3], q4 = sp[4], q5 = sp[5];
                    float s[24] = { q0.x,q0.y,q0.z,q0.w, q1.x,q1.y,q1.z,q1.w,
                                    q2.x,q2.y,q2.z,q2.w, q3.x,q3.y,q3.z,q3.w,
                                    q4.x,q4.y,q4.z,q4.w, q5.x,q5.y,q5.z,q5.w };
                    float v[21];
#pragma unroll
                    for (int i = 0; i < K; i++) v[i] = s[i] + tc[i];
                    const float m = max21(v);
                    unsigned e0 = 0, e1 = 0, e2 = 0;
#pragma unroll
                    for (int i = 0; i < 7; i++)   e0 |= (v[i] == m) ? (1u << i) : 0u;
#pragma unroll
                    for (int i = 7; i < 14; i++)  e1 |= (v[i] == m) ? (1u << i) : 0u;
#pragma unroll
                    for (int i = 14; i < 21; i++) e2 |= (v[i] == m) ? (1u << i) : 0u;
                    int bi = __ffs(e0 | e1 | e2) - 1;
                    bi = bi < 0 ? 0 : bi;
                    if (act) hist[(t - 1) * K + lane] = (unsigned char)bi;
                }
            }
        }
        __syncthreads();
    }

    // final chunk hist (warps 0 & 2) + svf; NLL on warp 1
    if (warp == 0 && act) svf[lane] = sc_s[(len - 1) * SC_STRIDE + lane] + endv[lane];

    if (warp == 0 || warp == 2) {
        int h0 = max(1, (nch - 1) * TCH);
        int off = (warp == 0) ? 0 : 1;
        for (int t = h0 + off; t < len; t += 2) {
            const float4* sp = (const float4*)(sc_s + (t - 1) * SC_STRIDE);
            float4 q0 = sp[0], q1 = sp[1], q2 = sp[2], q3 = sp[3], q4 = sp[4], q5 = sp[5];
            float s[24] = { q0.x,q0.y,q0.z,q0.w, q1.x,q1.y,q1.z,q1.w,
                            q2.x,q2.y,q2.z,q2.w, q3.x,q3.y,q3.z,q3.w,
                            q4.x,q4.y,q4.z,q4.w, q5.x,q5.y,q5.z,q5.w };
            float v[21];
#pragma unroll
            for (int i = 0; i < K; i++) v[i] = s[i] + tc[i];
            const float m = max21(v);
            unsigned e0 = 0, e1 = 0, e2 = 0;
#pragma unroll
            for (int i = 0; i < 7; i++)   e0 |= (v[i] == m) ? (1u << i) : 0u;
#pragma unroll
            for (int i = 7; i < 14; i++)  e1 |= (v[i] == m) ? (1u << i) : 0u;
#pragma unroll
            for (int i = 14; i < 21; i++) e2 |= (v[i] == m) ? (1u << i) : 0u;
            int bi = __ffs(e0 | e1 | e2) - 1;
            bi = bi < 0 ? 0 : bi;
            if (act) hist[(t - 1) * K + lane] = (unsigned char)bi;
        }
    } else if (warp == 1) {
        // denominator
        float vv = act ? (w * __expf(endv[lane])) : 0.0f;
#pragma unroll
        for (int o = 16; o > 0; o >>= 1) vv += __shfl_xor_sync(FULL, vv, o);
        const float den = C + __logf(vv);
        // numerator
        float part = 0.0f;
#pragma unroll
        for (int j = 0; j < 8; j++) {
            int up     = __shfl_up_sync(FULL, myt[j], 1);
            int prev31 = __shfl_sync(FULL, (j > 0) ? myt[j - 1] : 0, 31);
            int t  = j * 32 + lane;
            int tg = myt[j];
            int tp = (lane == 0) ? prev31 : up;
            if (tg != 0 && t >= 1) part += trans_s[tp * K + tg] + em_s[t * K + tg];
        }
#pragma unroll
        for (int o = 16; o > 0; o >>= 1) part += __shfl_down_sync(FULL, part, o);
        int lw = 0;
#pragma unroll
        for (int j = 0; j < 8; j++) if (((len - 1) >> 5) == j) lw = myt[j];
        int last = __shfl_sync(FULL, lw, (len - 1) & 31);
        int tag0 = __shfl_sync(FULL, myt[0], 0);
        if (lane == 0) {
            float num = start[tag0] + em_s[tag0] + part + endv[last];
            g_loss_partial[b] = den - num;
        }
    }
    __syncthreads();

    if (warp == 0) {
        if (lane == 0) {
            float m = NEG; int bi = 0;
            for (int i = 0; i < K; i++) { float cv = svf[i]; if (cv > m) { m = cv; bi = i; } }
            int cur = bi;
            path[len - 1] = (unsigned char)cur;
            for (int t = len - 2; t >= 0; t--) {
                cur = hist[t * K + cur];
                path[t] = (unsigned char)cur;
            }
        }
        __syncwarp();
#pragma unroll
        for (int j = 0; j < 8; j++) {
            int t = j * 32 + lane;
            int mk = (mw[j] >> lane) & 1;
            out[t * B + b] = mk ? (float)path[t] : 0.0f;
        }
    }
    __syncthreads();

    // end-of-block ticket: last scan block finalizes loss and resets counters
    if (tid == 0) {
        __threadfence();
        unsigned old = atomicAdd(&g_ticket, 1u);
        if (old == B - 1) {
            // ensure ALL gemm chunks are complete before resetting
            for (int cc = 0; cc < NCH; cc++) {
                while (*(volatile unsigned*)&g_chunk_done[cc] < CHUNK_TARGET) __nanosleep(64);
            }
            __threadfence();
            float s = 0.0f;
#pragma unroll 8
            for (int i = 0; i < B; i++) s += __ldcg(&g_loss_partial[i]);
            out[(size_t)T * B] = s;
            for (int cc = 0; cc < NCH; cc++) g_chunk_done[cc] = 0;
            __threadfence();
            atomicExch(&g_ticket, 0u);
        }
    }
}

// ---------------------------------------------------------------------------
extern "C" void kernel_launch(void* const* d_in, const int* in_sizes, int n_in,
                              void* d_out, int out_size)
{
    const float* feat  = (const float*)d_in[0];
    const int*   tags  = (const int*)  d_in[1];
    const float* W     = (const float*)d_in[2];
    const float* bias  = (const float*)d_in[3];
    const float* start = (const float*)d_in[4];
    const float* endv  = (const float*)d_in[5];
    const float* trans = (const float*)d_in[6];
    float* out = (float*)d_out;

    cudaFuncSetAttribute(fused_kernel,
                         cudaFuncAttributeMaxDynamicSharedMemorySize, SMEM_TOTAL_B);

    const int grid = B + (TB / GROWS) * DSPLIT;   // 128 scan + 1024 gemm
    fused_kernel<<<grid, GT, SMEM_TOTAL_B>>>(feat, W, tags, start, endv,
                                             trans, bias, out);
}

// round 14
// speedup vs baseline: 1.0082x; 1.0082x over previous
#include <cuda_runtime.h>

#define T 256
#define B 128
#define D 1024
#define K 21
#define TB (T * B)
#define TBK (TB * K)

#define DSPLIT 4
#define DCHUNK (D / DSPLIT)      // 256
#define DC 32
#define NSTAGE (DCHUNK / DC)     // 8
#define GROWS 128
#define GT 96

typedef unsigned long long ull;

// g_part layout: [split][b][t][k]
__device__ float g_part[DSPLIT * TBK];
__device__ float g_loss_partial[B];
__device__ unsigned g_ticket = 0;

__device__ __forceinline__ ull ffma2(ull a, ull b, ull c) {
    ull d;
    asm("fma.rn.f32x2 %0, %1, %2, %3;" : "=l"(d) : "l"(a), "l"(b), "l"(c));
    return d;
}
__device__ __forceinline__ ull pack2(float x, float y) {
    ull r;
    asm("mov.b64 %0, {%1, %2};" : "=l"(r) : "f"(x), "f"(y));
    return r;
}
__device__ __forceinline__ float2 unpack2(ull v) {
    float2 f;
    asm("mov.b64 {%0, %1}, %2;" : "=f"(f.x), "=f"(f.y) : "l"(v));
    return f;
}
__device__ __forceinline__ float max21(const float* v) {
    float a[11];
#pragma unroll
    for (int i = 0; i < 10; i++) a[i] = fmaxf(v[2 * i], v[2 * i + 1]);
    a[10] = v[20];
    float bb[6];
#pragma unroll
    for (int i = 0; i < 5; i++) bb[i] = fmaxf(a[2 * i], a[2 * i + 1]);
    bb[5] = a[10];
    float c0 = fmaxf(bb[0], bb[1]);
    float c1 = fmaxf(bb[2], bb[3]);
    float c2 = fmaxf(bb[4], bb[5]);
    return fmaxf(fmaxf(c0, c1), c2);
}

// ---------------------------------------------------------------------------
// Phase 1: partial GEMM — frozen R7/R9 configuration (DSPLIT=4).
// ---------------------------------------------------------------------------
__global__ __launch_bounds__(GT) void gemm_kernel(
    const float* __restrict__ A,      // [TB, D], row = t*B + b
    const float* __restrict__ Wg)     // [D, K]
{
    __shared__ ull        a_sh[DC * 65];
    __shared__ ulonglong2 w_sh[K * 16];

    const int tid = threadIdx.x;
    const int kg  = tid >> 5;
    const int rg  = tid & 31;
    const int rowblk = blockIdx.x >> 2;        // == t
    const int split  = blockIdx.x & 3;
    const int row0   = rowblk * GROWS;
    const int dbase  = split * DCHUNK;

    float4 apf[11];
    float2 wpf[4];

#pragma unroll
    for (int j = 0; j < 11; j++) {
        int i = tid + j * GT;
        if (i < 1024) {
            int r = i >> 3, dq = i & 7;
            apf[j] = *(const float4*)(A + (size_t)(row0 + r) * D + dbase + dq * 4);
        }
    }
#pragma unroll
    for (int j = 0; j < 4; j++) {
        int i = tid + j * GT;
        if (i < K * 16) {
            int k = i >> 4, dd2 = i & 15;
            int d0 = dbase + dd2 * 2;
            wpf[j].x = Wg[(size_t)d0 * K + k];
            wpf[j].y = Wg[(size_t)(d0 + 1) * K + k];
        }
    }

    ull acc0[7], acc1[7];
#pragma unroll
    for (int k = 0; k < 7; k++) { acc0[k] = 0ull; acc1[k] = 0ull; }

    for (int s = 0; s < NSTAGE; s++) {
        __syncthreads();
#pragma unroll
        for (int j = 0; j < 11; j++) {
            int i = tid + j * GT;
            if (i < 1024) {
                int r = i >> 3, dq = i & 7;
                int half = r >> 6, rl = r & 63;
                ((float*)&a_sh[(dq * 4 + 0) * 65 + rl])[half] = apf[j].x;
                ((float*)&a_sh[(dq * 4 + 1) * 65 + rl])[half] = apf[j].y;
                ((float*)&a_sh[(dq * 4 + 2) * 65 + rl])[half] = apf[j].z;
                ((float*)&a_sh[(dq * 4 + 3) * 65 + rl])[half] = apf[j].w;
            }
        }
#pragma unroll
        for (int j = 0; j < 4; j++) {
            int i = tid + j * GT;
            if (i < K * 16) {
                int k = i >> 4, dd2 = i & 15;
                w_sh[k * 16 + dd2] =
                    make_ulonglong2(pack2(wpf[j].x, wpf[j].x), pack2(wpf[j].y, wpf[j].y));
            }
        }
        if (s + 1 < NSTAGE) {
            int dcn = dbase + (s + 1) * DC;
#pragma unroll
            for (int j = 0; j < 11; j++) {
                int i = tid + j * GT;
                if (i < 1024) {
                    int r = i >> 3, dq = i & 7;
                    apf[j] = *(const float4*)(A + (size_t)(row0 + r) * D + dcn + dq * 4);
                }
            }
#pragma unroll
            for (int j = 0; j < 4; j++) {
                int i = tid + j * GT;
                if (i < K * 16) {
                    int k = i >> 4, dd2 = i & 15;
                    int d0 = dcn + dd2 * 2;
                    wpf[j].x = Wg[(size_t)d0 * K + k];
                    wpf[j].y = Wg[(size_t)(d0 + 1) * K + k];
                }
            }
        }
        __syncthreads();
        const ulonglong2* wk = w_sh + kg * 7 * 16;
#pragma unroll
        for (int dd2 = 0; dd2 < 16; dd2++) {
            ull a00 = a_sh[(2 * dd2) * 65 + rg];
            ull a01 = a_sh[(2 * dd2) * 65 + rg + 32];
            ull a10 = a_sh[(2 * dd2 + 1) * 65 + rg];
            ull a11 = a_sh[(2 * dd2 + 1) * 65 + rg + 32];
#pragma unroll
            for (int kk = 0; kk < 7; kk++) {
                ulonglong2 wv = wk[kk * 16 + dd2];
                acc0[kk] = ffma2(a00, wv.x, acc0[kk]);
                acc0[kk] = ffma2(a10, wv.y, acc0[kk]);
                acc1[kk] = ffma2(a01, wv.x, acc1[kk]);
                acc1[kk] = ffma2(a11, wv.y, acc1[kk]);
            }
        }
    }

    __syncthreads();
    float* e_sh = (float*)a_sh;
#pragma unroll
    for (int kk = 0; kk < 7; kk++) {
        int k = kg * 7 + kk;
        float2 v0 = unpack2(acc0[kk]);
        float2 v1 = unpack2(acc1[kk]);
        e_sh[(rg)      * K + k] = v0.x;
        e_sh[(rg + 64) * K + k] = v0.y;
        e_sh[(rg + 32) * K + k] = v1.x;
        e_sh[(rg + 96) * K + k] = v1.y;
    }
    __syncthreads();
    float* gp = g_part + (size_t)split * TBK;
#pragma unroll
    for (int j = 0; j < (GROWS * K) / GT; j++) {
        int e = tid + j * GT;
        int bb = e / K;
        int k  = e - bb * K;
        gp[((size_t)bb * T + rowblk) * K + k] = e_sh[e];
    }
}

// ---------------------------------------------------------------------------
// Phase 2: role-split scan. grid = 2B. Even blocks: Viterbi (3 warps).
// Odd blocks: forward + NLL (2 warps, chain on warp 0). Each chain gets
// (mostly) a private SM -> no cross-chain MIO contention.
// Chain code is verbatim from R11 (passing).
// ---------------------------------------------------------------------------
#define SC_STRIDE 24
#define SMEM_EM     0
#define SMEM_SC     (T * K)
#define SMEM_TRANS  (SMEM_SC + T * SC_STRIDE)
#define SMEM_RMAX   (SMEM_TRANS + 444)
#define SMEM_SVF    (SMEM_RMAX + T)
#define SMEM_WB     (SMEM_SVF + 32)
#define SMEM_FLOATS (SMEM_WB + 64)
#define SMEM_HIST_B (SMEM_FLOATS * 4)
#define SMEM_PATH_B (SMEM_HIST_B + (T - 1) * K)
#define SMEM_TOTAL_B (SMEM_PATH_B + T + 16)

__global__ __launch_bounds__(96) void scan_kernel(
    const int*   __restrict__ tags,
    const float* __restrict__ start,
    const float* __restrict__ endv,
    const float* __restrict__ trans,
    const float* __restrict__ bias,
    float* __restrict__ out)
{
    extern __shared__ __align__(16) char smraw[];
    float* em_s    = (float*)smraw + SMEM_EM;
    float* sc_s    = (float*)smraw + SMEM_SC;
    float* trans_s = (float*)smraw + SMEM_TRANS;
    float* rmax_s  = (float*)smraw + SMEM_RMAX;
    float* svf     = (float*)smraw + SMEM_SVF;
    float* wb0     = (float*)smraw + SMEM_WB;
    float* wb1     = (float*)smraw + SMEM_WB + 32;
    unsigned char* hist = (unsigned char*)smraw + SMEM_HIST_B;
    unsigned char* path = (unsigned char*)smraw + SMEM_PATH_B;

    const int b    = blockIdx.x >> 1;
    const int role = blockIdx.x & 1;          // 0 = viterbi, 1 = forward
    const int warp = threadIdx.x >> 5;
    const int lane = threadIdx.x & 31;
    const int tid  = threadIdx.x;
    const bool act = (lane < K);
    const float NEG = -1e30f;
    const unsigned FULL = 0xffffffffu;

    __shared__ float bias_s[K];
    if (tid < K) bias_s[tid] = bias[tid];
    for (int i = tid; i < K * K; i += 96) trans_s[i] = trans[i];
    __syncthreads();

    // Stage emissions: coalesced float4 reads of the 4 split partials + bias.
    {
        const size_t base = (size_t)b * T * K;
        const float4* p0 = (const float4*)(g_part + base);
        const float4* p1 = (const float4*)(g_part + base + TBK);
        const float4* p2 = (const float4*)(g_part + base + 2 * (size_t)TBK);
        const float4* p3 = (const float4*)(g_part + base + 3 * (size_t)TBK);
        float4* dst = (float4*)em_s;
        for (int i = tid; i < (T * K) / 4; i += 96) {
            float4 a = p0[i], c = p1[i], d = p2[i], e = p3[i];
            int e0 = i * 4;
            int k0 = e0 % K;
            int k1 = k0 + 1; if (k1 >= K) k1 -= K;
            int k2 = k1 + 1; if (k2 >= K) k2 -= K;
            int k3 = k2 + 1; if (k3 >= K) k3 -= K;
            float4 r;
            r.x = ((a.x + c.x) + (d.x + e.x)) + bias_s[k0];
            r.y = ((a.y + c.y) + (d.y + e.y)) + bias_s[k1];
            r.z = ((a.z + c.z) + (d.z + e.z)) + bias_s[k2];
            r.w = ((a.w + c.w) + (d.w + e.w)) + bias_s[k3];
            dst[i] = r;
        }
    }

    // Per-warp tags + ballot masks. Mask is a PREFIX: len = popcount.
    int myt[8];
    unsigned mw[8];
#pragma unroll
    for (int j = 0; j < 8; j++) {
        myt[j] = tags[(j * 32 + lane) * B + b];
        mw[j]  = __ballot_sync(FULL, myt[j] != 0);
    }
    int len = 0;
#pragma unroll
    for (int j = 0; j < 8; j++) len += __popc(mw[j]);
    __syncthreads();

    if (role == 1) {
        // =================== FORWARD block ===================
        for (int t = tid; t < T; t += 96) {
            const float* p = em_s + t * K;
            float m = p[0];
#pragma unroll
            for (int i = 1; i < K; i++) m = fmaxf(m, p[i]);
            rmax_s[t] = m;
        }
        __syncthreads();
        if (warp != 0) return;

        float et[K];
#pragma unroll
        for (int i = 0; i < K; i++) et[i] = act ? __expf(trans_s[i * K + lane]) : 0.0f;

        float sc0 = act ? (start[lane] + em_s[lane]) : NEG;
        float r0 = sc0;
#pragma unroll
        for (int o = 16; o > 0; o >>= 1) r0 = fmaxf(r0, __shfl_xor_sync(FULL, r0, o));
        float w = act ? __expf(sc0 - r0) : 0.0f;
        float C = r0;

        float rN   = rmax_s[1];
        float eemN = act ? __expf(em_s[K + lane] - rN) : 0.0f;

        for (int t = 1; t < len; t++) {
            const float eem = eemN;
            const float r   = rN;
            float* buf = (t & 1) ? wb1 : wb0;
            if (act) buf[lane] = w;
            __syncwarp();
            if (t + 1 < len) {
                rN   = rmax_s[t + 1];
                eemN = act ? __expf(em_s[(t + 1) * K + lane] - rN) : 0.0f;
            }
            const float4* bp = (const float4*)buf;
            float4 q0 = bp[0], q1 = bp[1], q2 = bp[2], q3 = bp[3], q4 = bp[4], q5 = bp[5];
            float wv[24] = { q0.x,q0.y,q0.z,q0.w, q1.x,q1.y,q1.z,q1.w,
                             q2.x,q2.y,q2.z,q2.w, q3.x,q3.y,q3.z,q3.w,
                             q4.x,q4.y,q4.z,q4.w, q5.x,q5.y,q5.z,q5.w };
            float d0 = 0.f, d1 = 0.f, d2 = 0.f;
#pragma unroll
            for (int i = 0; i < 7; i++)   d0 = fmaf(wv[i], et[i], d0);
#pragma unroll
            for (int i = 7; i < 14; i++)  d1 = fmaf(wv[i], et[i], d1);
#pragma unroll
            for (int i = 14; i < 21; i++) d2 = fmaf(wv[i], et[i], d2);
            w = ((d0 + d1) + d2) * eem;
            C += r;
            if ((t & 7) == 7) {
                float S = w;
#pragma unroll
                for (int o = 16; o > 0; o >>= 1) S += __shfl_xor_sync(FULL, S, o);
                float rs;
                asm("rcp.approx.f32 %0, %1;" : "=f"(rs) : "f"(S));
                w *= rs;
                C += __logf(S);
            }
        }

        float vv = act ? (w * __expf(endv[lane])) : 0.0f;
#pragma unroll
        for (int o = 16; o > 0; o >>= 1) vv += __shfl_xor_sync(FULL, vv, o);
        const float den = C + __logf(vv);

        float part = 0.0f;
#pragma unroll
        for (int j = 0; j < 8; j++) {
            int up     = __shfl_up_sync(FULL, myt[j], 1);
            int prev31 = __shfl_sync(FULL, (j > 0) ? myt[j - 1] : 0, 31);
            int t  = j * 32 + lane;
            int tg = myt[j];
            int tp = (lane == 0) ? prev31 : up;
            if (tg != 0 && t >= 1) {
                part += trans_s[tp * K + tg] + em_s[t * K + tg];
            }
        }
#pragma unroll
        for (int o = 16; o > 0; o >>= 1) part += __shfl_down_sync(FULL, part, o);

        int lw = 0;
#pragma unroll
        for (int j = 0; j < 8; j++) if (((len - 1) >> 5) == j) lw = myt[j];
        int last = __shfl_sync(FULL, lw, (len - 1) & 31);
        int tag0 = __shfl_sync(FULL, myt[0], 0);

        if (lane == 0) {
            float num = start[tag0] + em_s[tag0] + part + endv[last];
            g_loss_partial[b] = den - num;
            __threadfence();
            unsigned old = atomicAdd(&g_ticket, 1u);
            if (old == B - 1) {
                __threadfence();
                float s = 0.0f;
#pragma unroll 8
                for (int i = 0; i < B; i++) s += __ldcg(&g_loss_partial[i]);
                out[(size_t)T * B] = s;
                atomicExch(&g_ticket, 0u);
            }
        }
        return;
    }

    // =================== VITERBI block (warps 0,1,2) ===================
    float tc[K];
#pragma unroll
    for (int i = 0; i < K; i++) tc[i] = act ? trans_s[i * K + lane] : 0.0f;

    if (warp == 0) {
        // Chain: state in sc_s; broadcast via LDS.128 (R11 verbatim).
        if (act) sc_s[lane] = start[lane] + em_s[lane];
        __syncwarp();

        float emN = act ? em_s[K + lane] : 0.0f;
        for (int t = 1; t < len; t++) {
            const float em_t = emN;
            if (t + 1 < len) emN = act ? em_s[(t + 1) * K + lane] : 0.0f;

            const float4* sp = (const float4*)(sc_s + (t - 1) * SC_STRIDE);
            float4 q0 = sp[0], q1 = sp[1], q2 = sp[2], q3 = sp[3], q4 = sp[4], q5 = sp[5];
            float s[24] = { q0.x,q0.y,q0.z,q0.w, q1.x,q1.y,q1.z,q1.w,
                            q2.x,q2.y,q2.z,q2.w, q3.x,q3.y,q3.z,q3.w,
                            q4.x,q4.y,q4.z,q4.w, q5.x,q5.y,q5.z,q5.w };
            float v[21];
#pragma unroll
            for (int i = 0; i < K; i++) v[i] = s[i] + tc[i];
            const float m = max21(v);

            if (act) sc_s[t * SC_STRIDE + lane] = m + em_t;
            __syncwarp();
        }
        float scl = act ? sc_s[(len - 1) * SC_STRIDE + lane] : NEG;
        svf[lane] = act ? (scl + endv[lane]) : NEG;
        __syncwarp();
    }

    asm volatile("bar.sync 1, 96;" ::: "memory");

    // Parallel hist recompute (3-way split over t).
    for (int t = 1 + warp; t < len; t += 3) {
        const float4* sp = (const float4*)(sc_s + (t - 1) * SC_STRIDE);
        float4 q0 = sp[0], q1 = sp[1], q2 = sp[2], q3 = sp[3], q4 = sp[4], q5 = sp[5];
        float s[24] = { q0.x,q0.y,q0.z,q0.w, q1.x,q1.y,q1.z,q1.w,
                        q2.x,q2.y,q2.z,q2.w, q3.x,q3.y,q3.z,q3.w,
                        q4.x,q4.y,q4.z,q4.w, q5.x,q5.y,q5.z,q5.w };
        float v[21];
#pragma unroll
        for (int i = 0; i < K; i++) v[i] = s[i] + tc[i];
        const float m = max21(v);

        unsigned e0 = 0, e1 = 0, e2 = 0;
#pragma unroll
        for (int i = 0; i < 7; i++)   e0 |= (v[i] == m) ? (1u << i) : 0u;
#pragma unroll
        for (int i = 7; i < 14; i++)  e1 |= (v[i] == m) ? (1u << i) : 0u;
#pragma unroll
        for (int i = 14; i < 21; i++) e2 |= (v[i] == m) ? (1u << i) : 0u;
        int bi = __ffs(e0 | e1 | e2) - 1;
        bi = bi < 0 ? 0 : bi;

        if (act) hist[(t - 1) * K + lane] = (unsigned char)bi;
    }

    asm volatile("bar.sync 1, 96;" ::: "memory");

    if (warp == 0) {
        if (lane == 0) {
            float m = NEG; int bi = 0;
            for (int i = 0; i < K; i++) { float c = svf[i]; if (c > m) { m = c; bi = i; } }
            int cur = bi;
            path[len - 1] = (unsigned char)cur;
            for (int t = len - 2; t >= 0; t--) {
                cur = hist[t * K + cur];
                path[t] = (unsigned char)cur;
            }
        }
        __syncwarp();
#pragma unroll
        for (int j = 0; j < 8; j++) {
            int t = j * 32 + lane;
            int mk = (mw[j] >> lane) & 1;
            out[t * B + b] = mk ? (float)path[t] : 0.0f;
        }
    }
}

// ---------------------------------------------------------------------------
extern "C" void kernel_launch(void* const* d_in, const int* in_sizes, int n_in,
                              void* d_out, int out_size)
{
    const float* feat  = (const float*)d_in[0];
    const int*   tags  = (const int*)  d_in[1];
    const float* W     = (const float*)d_in[2];
    const float* bias  = (const float*)d_in[3];
    const float* start = (const float*)d_in[4];
    const float* endv  = (const float*)d_in[5];
    const float* trans = (const float*)d_in[6];
    float* out = (float*)d_out;

    cudaFuncSetAttribute(scan_kernel,
                         cudaFuncAttributeMaxDynamicSharedMemorySize, SMEM_TOTAL_B);

    gemm_kernel<<<(TB / GROWS) * DSPLIT, GT>>>(feat, W);
    scan_kernel<<<2 * B, 96, SMEM_TOTAL_B>>>(tags, start, endv, trans, bias, out);
}